// round 7
// baseline (speedup 1.0000x reference)
#include <cuda_runtime.h>
#include <cuda_bf16.h>
#include <cstdint>
#include <cstddef>

#define T_STEPS 512
#define B_BATCH 128
#define D_IN    512
#define H_DIM   512

// ---------------- device scratch (no-alloc rule) ----------------
__device__ float          g_xproj[(size_t)T_STEPS * B_BATCH * 3 * H_DIM]; // [T,B,3H]
__device__ __nv_bfloat16  g_hhi[2][(size_t)B_BATCH * H_DIM];  // [buf][row][k]
__device__ __nv_bfloat16  g_hlo[2][(size_t)B_BATCH * H_DIM];
__device__ float          g_hfp[(size_t)B_BATCH * H_DIM];     // fp32 h (row-major)
__device__ float          g_partial[(size_t)32 * 2 * 3 * 128 * 48];
__device__ unsigned       g_bar[T_STEPS];                     // 32 producers/step
__device__ unsigned       g_pflag[T_STEPS][32];               // 3 peers per (t,hs)

// ---------- helpers ----------
static __device__ __forceinline__ uint32_t smem_u32(const void* p) {
    uint32_t a;
    asm("{ .reg .u64 t; cvta.to.shared.u64 t, %1; cvt.u32.u64 %0, t; }"
        : "=r"(a) : "l"(p));
    return a;
}
static __device__ __forceinline__ void ldsm_x4(uint32_t& r0, uint32_t& r1,
                                               uint32_t& r2, uint32_t& r3,
                                               uint32_t addr) {
    asm volatile("ldmatrix.sync.aligned.m8n8.x4.shared.b16 {%0,%1,%2,%3}, [%4];"
                 : "=r"(r0), "=r"(r1), "=r"(r2), "=r"(r3) : "r"(addr));
}
static __device__ __forceinline__ void ldsm_x2(uint32_t& r0, uint32_t& r1,
                                               uint32_t addr) {
    asm volatile("ldmatrix.sync.aligned.m8n8.x2.shared.b16 {%0,%1}, [%2];"
                 : "=r"(r0), "=r"(r1) : "r"(addr));
}
static __device__ __forceinline__ void mma_bf16(float& c0, float& c1, float& c2, float& c3,
                                                uint32_t a0, uint32_t a1, uint32_t a2, uint32_t a3,
                                                uint32_t b0, uint32_t b1) {
    asm volatile("mma.sync.aligned.m16n8k16.row.col.f32.bf16.bf16.f32 "
                 "{%0,%1,%2,%3}, {%4,%5,%6,%7}, {%8,%9}, {%0,%1,%2,%3};"
                 : "+f"(c0), "+f"(c1), "+f"(c2), "+f"(c3)
                 : "r"(a0), "r"(a1), "r"(a2), "r"(a3), "r"(b0), "r"(b1));
}
static __device__ __forceinline__ uint32_t bf16x2_of(float lo, float hi) {
    __nv_bfloat16 a = __float2bfloat16_rn(lo);
    __nv_bfloat16 b = __float2bfloat16_rn(hi);
    return (uint32_t)__bfloat16_as_ushort(a) | ((uint32_t)__bfloat16_as_ushort(b) << 16);
}

// ---------- prep: zero flags; planes/hfp from h0 ----------
__global__ void scan_prep_kernel(const float* __restrict__ h0) {
    if (blockIdx.x == 0) {
        for (int i = threadIdx.x; i < T_STEPS; i += 256) g_bar[i] = 0u;
        for (int i = threadIdx.x; i < T_STEPS * 32; i += 256)
            ((unsigned*)g_pflag)[i] = 0u;
    } else {
        int idx = (blockIdx.x - 1) * 256 + threadIdx.x;   // row-major [row][k]
        float v = h0[idx];
        __nv_bfloat16 hi = __float2bfloat16_rn(v);
        g_hfp[idx] = v;
        g_hhi[1][idx] = hi;
        g_hlo[1][idx] = __float2bfloat16_rn(v - __bfloat162float(hi));
    }
}

// ---------------- x_proj GEMM via mma.sync split-bf16 (round-6, passing) ----------------
#define XP_ROWSTR 40
#define XP_PLANE  (128 * XP_ROWSTR)
#define XP_BUF    (4 * XP_PLANE)
#define XP_SMEM_BYTES (2 * XP_BUF * 2)

__global__ __launch_bounds__(256, 1) void xproj_kernel(const float* __restrict__ A,
                                                       const float* __restrict__ W,
                                                       const float* __restrict__ bi) {
    extern __shared__ __align__(16) __nv_bfloat16 sm[];
    const int tid = threadIdx.x;
    const int lane = tid & 31;
    const int wid = tid >> 5;
    const int warp_m = wid & 1;
    const int warp_n = wid >> 1;
    const int m0 = blockIdx.y * 128;
    const int n0 = blockIdx.x * 128;

    float acc[4][4][4];
#pragma unroll
    for (int i = 0; i < 4; ++i)
#pragma unroll
        for (int jn = 0; jn < 4; ++jn)
#pragma unroll
            for (int q = 0; q < 4; ++q) acc[i][jn][q] = 0.f;

    float2 ra[8];
    float  rw0[8], rw1[8];

    const uint32_t a_lane_off = (uint32_t)((lane & 15) * (XP_ROWSTR * 2) + (lane >> 4) * 16);
    const uint32_t b_lane_off = (uint32_t)(((lane & 7) + ((lane >> 4) << 3)) * (XP_ROWSTR * 2)
                                           + ((lane >> 3) & 1) * 16);
    const uint32_t sm_base = smem_u32(sm);

    {
        const int k0 = 0;
#pragma unroll
        for (int i = 0; i < 8; ++i) {
            int p = i * 256 + tid;
            int r = p >> 4, cp = p & 15;
            ra[i] = *(const float2*)&A[(size_t)(m0 + r) * D_IN + k0 + cp * 2];
            int n = p & 127, kp = p >> 7;
            rw0[i] = W[(size_t)(k0 + 2 * kp) * 1536 + n0 + n];
            rw1[i] = W[(size_t)(k0 + 2 * kp + 1) * 1536 + n0 + n];
        }
        uint32_t* AH = (uint32_t*)(sm);
        uint32_t* AL = (uint32_t*)(sm + XP_PLANE);
        uint32_t* WH = (uint32_t*)(sm + 2 * XP_PLANE);
        uint32_t* WL = (uint32_t*)(sm + 3 * XP_PLANE);
#pragma unroll
        for (int i = 0; i < 8; ++i) {
            int p = i * 256 + tid;
            int r = p >> 4, cp = p & 15;
            float h0v = __bfloat162float(__float2bfloat16_rn(ra[i].x));
            float h1v = __bfloat162float(__float2bfloat16_rn(ra[i].y));
            AH[r * (XP_ROWSTR / 2) + cp] = bf16x2_of(ra[i].x, ra[i].y);
            AL[r * (XP_ROWSTR / 2) + cp] = bf16x2_of(ra[i].x - h0v, ra[i].y - h1v);
            int n = p & 127, kp = p >> 7;
            float w0h = __bfloat162float(__float2bfloat16_rn(rw0[i]));
            float w1h = __bfloat162float(__float2bfloat16_rn(rw1[i]));
            WH[n * (XP_ROWSTR / 2) + kp] = bf16x2_of(rw0[i], rw1[i]);
            WL[n * (XP_ROWSTR / 2) + kp] = bf16x2_of(rw0[i] - w0h, rw1[i] - w1h);
        }
    }
    __syncthreads();

    int buf = 0;
    for (int kt = 0; kt < 16; ++kt) {
        if (kt < 15) {
            const int k0 = (kt + 1) * 32;
#pragma unroll
            for (int i = 0; i < 8; ++i) {
                int p = i * 256 + tid;
                int r = p >> 4, cp = p & 15;
                ra[i] = *(const float2*)&A[(size_t)(m0 + r) * D_IN + k0 + cp * 2];
                int n = p & 127, kp = p >> 7;
                rw0[i] = W[(size_t)(k0 + 2 * kp) * 1536 + n0 + n];
                rw1[i] = W[(size_t)(k0 + 2 * kp + 1) * 1536 + n0 + n];
            }
        }
        const uint32_t bb = sm_base + (uint32_t)(buf * XP_BUF * 2);
        const uint32_t baseAH = bb;
        const uint32_t baseAL = bb + XP_PLANE * 2;
        const uint32_t baseWH = bb + 2 * XP_PLANE * 2;
        const uint32_t baseWL = bb + 3 * XP_PLANE * 2;
#pragma unroll
        for (int k16 = 0; k16 < 2; ++k16) {
            const uint32_t kadd = (uint32_t)(k16 * 32);
            uint32_t ah[4][4], al[4][4], bh[4][2], bl[4][2];
#pragma unroll
            for (int mt = 0; mt < 4; ++mt) {
                uint32_t ro = (uint32_t)((warp_m * 64 + mt * 16) * (XP_ROWSTR * 2));
                ldsm_x4(ah[mt][0], ah[mt][1], ah[mt][2], ah[mt][3],
                        baseAH + ro + a_lane_off + kadd);
                ldsm_x4(al[mt][0], al[mt][1], al[mt][2], al[mt][3],
                        baseAL + ro + a_lane_off + kadd);
            }
#pragma unroll
            for (int nt2 = 0; nt2 < 2; ++nt2) {
                uint32_t no = (uint32_t)((warp_n * 32 + nt2 * 16) * (XP_ROWSTR * 2));
                ldsm_x4(bh[nt2 * 2][0], bh[nt2 * 2][1], bh[nt2 * 2 + 1][0], bh[nt2 * 2 + 1][1],
                        baseWH + no + b_lane_off + kadd);
                ldsm_x4(bl[nt2 * 2][0], bl[nt2 * 2][1], bl[nt2 * 2 + 1][0], bl[nt2 * 2 + 1][1],
                        baseWL + no + b_lane_off + kadd);
            }
#pragma unroll
            for (int mt = 0; mt < 4; ++mt)
#pragma unroll
                for (int nt = 0; nt < 4; ++nt) {
                    float* c = acc[mt][nt];
                    mma_bf16(c[0], c[1], c[2], c[3],
                             ah[mt][0], ah[mt][1], ah[mt][2], ah[mt][3],
                             bh[nt][0], bh[nt][1]);
                    mma_bf16(c[0], c[1], c[2], c[3],
                             al[mt][0], al[mt][1], al[mt][2], al[mt][3],
                             bh[nt][0], bh[nt][1]);
                    mma_bf16(c[0], c[1], c[2], c[3],
                             ah[mt][0], ah[mt][1], ah[mt][2], ah[mt][3],
                             bl[nt][0], bl[nt][1]);
                }
        }
        if (kt < 15) {
            __syncthreads();
            int nb = buf ^ 1;
            __nv_bfloat16* sb = sm + nb * XP_BUF;
            uint32_t* AH = (uint32_t*)(sb);
            uint32_t* AL = (uint32_t*)(sb + XP_PLANE);
            uint32_t* WH = (uint32_t*)(sb + 2 * XP_PLANE);
            uint32_t* WL = (uint32_t*)(sb + 3 * XP_PLANE);
#pragma unroll
            for (int i = 0; i < 8; ++i) {
                int p = i * 256 + tid;
                int r = p >> 4, cp = p & 15;
                float h0v = __bfloat162float(__float2bfloat16_rn(ra[i].x));
                float h1v = __bfloat162float(__float2bfloat16_rn(ra[i].y));
                AH[r * (XP_ROWSTR / 2) + cp] = bf16x2_of(ra[i].x, ra[i].y);
                AL[r * (XP_ROWSTR / 2) + cp] = bf16x2_of(ra[i].x - h0v, ra[i].y - h1v);
                int n = p & 127, kp = p >> 7;
                float w0h = __bfloat162float(__float2bfloat16_rn(rw0[i]));
                float w1h = __bfloat162float(__float2bfloat16_rn(rw1[i]));
                WH[n * (XP_ROWSTR / 2) + kp] = bf16x2_of(rw0[i], rw1[i]);
                WL[n * (XP_ROWSTR / 2) + kp] = bf16x2_of(rw0[i] - w0h, rw1[i] - w1h);
            }
            __syncthreads();
            buf = nb;
        }
    }

#pragma unroll
    for (int nt = 0; nt < 4; ++nt) {
        int ncol = warp_n * 32 + nt * 8 + (lane & 3) * 2;
        float2 bv = *(const float2*)&bi[n0 + ncol];
#pragma unroll
        for (int mt = 0; mt < 4; ++mt) {
            int r = m0 + warp_m * 64 + mt * 16 + (lane >> 2);
            float* c = acc[mt][nt];
            float2 o0; o0.x = c[0] + bv.x; o0.y = c[1] + bv.y;
            float2 o1; o1.x = c[2] + bv.x; o1.y = c[3] + bv.y;
            *(float2*)&g_xproj[(size_t)r * 1536 + n0 + ncol] = o0;
            *(float2*)&g_xproj[(size_t)(r + 8) * 1536 + n0 + ncol] = o1;
        }
    }
}

// ---------------- persistent mma.sync GRU scan ----------------
// 128 CTAs: hs = bid>>2 (16 hid cols -> N=48), kc = bid&3 (K-chunk of 128).
// Warp grid 4(M)x2(N): warp tile m32 x n24. Split-bf16: Ah@Wh + Al@Wh + Ah@Wl.
// kc!=0 -> gmem partial + flag; kc==0 -> reduce, gates, publish h planes, barrier.
#define SC_STR   272                       // smem row stride bytes (128 bf16 + pad)
#define SM_AH    0
#define SM_AL    (128 * SC_STR)            // 34816
#define SM_WH    (2 * 128 * SC_STR)        // 69632
#define SM_WL    (SM_WH + 48 * SC_STR)     // 82688
#define SM_DS    (SM_WH + 2 * 48 * SC_STR) // 95744 (fp32 D [128][50])
#define SC_SMEM  (SM_DS + 128 * 50 * 4)    // 121344

__global__ __launch_bounds__(256, 1) void gru_kernel(const int* __restrict__ resets,
                                                     const float* __restrict__ Whrz,
                                                     const float* __restrict__ Whn,
                                                     const float* __restrict__ bhn,
                                                     float* out) {
    extern __shared__ __align__(16) char smc[];
    const uint32_t sb = smem_u32(smc);
    float* Ds = (float*)(smc + SM_DS);
    __shared__ float bn_s[16];

    const int tid = threadIdx.x;
    const int lane = tid & 31;
    const int wid = tid >> 5;
    const int warp_m = wid & 3;            // m32 group
    const int warp_n = wid >> 2;           // n24 group
    const int hs = blockIdx.x >> 2;
    const int kc = blockIdx.x & 3;
    const int j0 = hs * 16;

    float* hT = out;
    float* ys = out + (size_t)B_BATCH * H_DIM;

    if (tid < 16) bn_s[tid] = bhn[j0 + tid];

    // one-time: W slice (48 x 128) -> smem hi/lo bf16, layout [n][k] stride 272B
    for (int idx = tid; idx < 48 * 128; idx += 256) {
        int n = idx >> 7;
        int kl = idx & 127;
        int k = kc * 128 + kl;
        int gate = n >> 4;
        int col = j0 + (n & 15);
        float w;
        if (gate == 0)      w = Whrz[(size_t)k * 1024 + col];
        else if (gate == 1) w = Whrz[(size_t)k * 1024 + 512 + col];
        else                w = Whn[(size_t)k * 512 + col];
        __nv_bfloat16 whi = __float2bfloat16_rn(w);
        *(__nv_bfloat16*)(smc + SM_WH + n * SC_STR + kl * 2) = whi;
        *(__nv_bfloat16*)(smc + SM_WL + n * SC_STR + kl * 2) =
            __float2bfloat16_rn(w - __bfloat162float(whi));
    }
    __syncthreads();

    // ldmatrix lane offsets
    const uint32_t a_off = (uint32_t)((lane & 15) * SC_STR + (lane >> 4) * 16);
    const uint32_t b4_off = (uint32_t)(((lane & 7) + ((lane >> 4) << 3)) * SC_STR
                                       + ((lane >> 3) & 1) * 16);
    const uint32_t b2_off = (uint32_t)(((lane & 15) & 7) * SC_STR + (((lane & 15) >> 3) & 1) * 16);

    // staging role: row = tid>>1, k-half = (tid&1)*64
    const int srow = tid >> 1;
    const int skh = (tid & 1) * 64;

    for (int t = 0; t < T_STEPS; ++t) {
        // prefetch gate inputs (kc==0, tid<128)
        float xrv[16], xzv[16], xnv[16];
        if (kc == 0 && tid < 128) {
            const float* xb = g_xproj + ((size_t)t * B_BATCH + tid) * 1536 + j0;
#pragma unroll
            for (int q = 0; q < 4; ++q) {
                float4 a = __ldcs((const float4*)(xb) + q);
                float4 b = __ldcs((const float4*)(xb + 512) + q);
                float4 c = __ldcs((const float4*)(xb + 1024) + q);
                xrv[q*4+0]=a.x; xrv[q*4+1]=a.y; xrv[q*4+2]=a.z; xrv[q*4+3]=a.w;
                xzv[q*4+0]=b.x; xzv[q*4+1]=b.y; xzv[q*4+2]=b.z; xzv[q*4+3]=b.w;
                xnv[q*4+0]=c.x; xnv[q*4+1]=c.y; xnv[q*4+2]=c.z; xnv[q*4+3]=c.w;
            }
        }

        // step barrier: wait for all 32 producers of step t-1
        if (t > 0 && tid == 0) {
            volatile unsigned* vb = &g_bar[t - 1];
            while (*vb < 32u) __nanosleep(32);
        }
        __syncthreads();

        // stage masked A chunk [128 rows][128 k] hi/lo from planes buf[(t-1)&1]
        {
            const int pb = (t + 1) & 1;
            const bool rst = resets[t * B_BATCH + srow] != 0;
            const size_t go = (size_t)srow * H_DIM + kc * 128 + skh;
            const uint4* ph = (const uint4*)(g_hhi[pb] + go);
            const uint4* pl = (const uint4*)(g_hlo[pb] + go);
            char* dh = smc + SM_AH + srow * SC_STR + skh * 2;
            char* dl = smc + SM_AL + srow * SC_STR + skh * 2;
#pragma unroll
            for (int i = 0; i < 8; ++i) {
                uint4 vh = __ldcg(ph + i);
                uint4 vl = __ldcg(pl + i);
                if (rst) { vh.x = vh.y = vh.z = vh.w = 0u; vl = vh; }
                *(uint4*)(dh + i * 16) = vh;
                *(uint4*)(dl + i * 16) = vl;
            }
        }
        __syncthreads();

        // MMA: warp tile m32 x n24, K=128, 3 split terms
        float acc[2][3][4];
#pragma unroll
        for (int mt = 0; mt < 2; ++mt)
#pragma unroll
            for (int nt = 0; nt < 3; ++nt)
#pragma unroll
                for (int q = 0; q < 4; ++q) acc[mt][nt][q] = 0.f;

        const uint32_t baseA = sb + (uint32_t)(warp_m * 32 * SC_STR);
        const uint32_t baseB = sb + (uint32_t)(warp_n * 24 * SC_STR);
#pragma unroll
        for (int k16 = 0; k16 < 8; ++k16) {
            const uint32_t kadd = (uint32_t)(k16 * 32);
            uint32_t ah[2][4], al[2][4], bh[3][2], bl[3][2];
#pragma unroll
            for (int mt = 0; mt < 2; ++mt) {
                uint32_t ro = (uint32_t)(mt * 16 * SC_STR) + a_off + kadd;
                ldsm_x4(ah[mt][0], ah[mt][1], ah[mt][2], ah[mt][3], baseA + SM_AH + ro);
                ldsm_x4(al[mt][0], al[mt][1], al[mt][2], al[mt][3], baseA + SM_AL + ro);
            }
            ldsm_x4(bh[0][0], bh[0][1], bh[1][0], bh[1][1], baseB + SM_WH + b4_off + kadd);
            ldsm_x2(bh[2][0], bh[2][1], baseB + SM_WH + (uint32_t)(16 * SC_STR) + b2_off + kadd);
            ldsm_x4(bl[0][0], bl[0][1], bl[1][0], bl[1][1], baseB + SM_WL + b4_off + kadd);
            ldsm_x2(bl[2][0], bl[2][1], baseB + SM_WL + (uint32_t)(16 * SC_STR) + b2_off + kadd);
#pragma unroll
            for (int mt = 0; mt < 2; ++mt)
#pragma unroll
                for (int nt = 0; nt < 3; ++nt) {
                    float* c = acc[mt][nt];
                    mma_bf16(c[0], c[1], c[2], c[3],
                             ah[mt][0], ah[mt][1], ah[mt][2], ah[mt][3],
                             bh[nt][0], bh[nt][1]);
                    mma_bf16(c[0], c[1], c[2], c[3],
                             al[mt][0], al[mt][1], al[mt][2], al[mt][3],
                             bh[nt][0], bh[nt][1]);
                    mma_bf16(c[0], c[1], c[2], c[3],
                             ah[mt][0], ah[mt][1], ah[mt][2], ah[mt][3],
                             bl[nt][0], bl[nt][1]);
                }
        }

        if (kc != 0) {
            // write fp32 partial [128][48] to gmem, then flag
            float* pp = g_partial + ((((size_t)hs * 2 + (t & 1)) * 3 + (kc - 1)) * 128) * 48;
#pragma unroll
            for (int mt = 0; mt < 2; ++mt) {
                int r = warp_m * 32 + mt * 16 + (lane >> 2);
#pragma unroll
                for (int nt = 0; nt < 3; ++nt) {
                    int cc = warp_n * 24 + nt * 8 + (lane & 3) * 2;
                    float* c = acc[mt][nt];
                    *(float2*)&pp[(size_t)r * 48 + cc] = make_float2(c[0], c[1]);
                    *(float2*)&pp[(size_t)(r + 8) * 48 + cc] = make_float2(c[2], c[3]);
                }
            }
            __threadfence();
            __syncthreads();
            if (tid == 0) atomicAdd(&g_pflag[t][hs], 1u);
        } else {
            // own fragments -> smem Ds [128][50]
#pragma unroll
            for (int mt = 0; mt < 2; ++mt) {
                int r = warp_m * 32 + mt * 16 + (lane >> 2);
#pragma unroll
                for (int nt = 0; nt < 3; ++nt) {
                    int cc = warp_n * 24 + nt * 8 + (lane & 3) * 2;
                    float* c = acc[mt][nt];
                    *(float2*)&Ds[r * 50 + cc] = make_float2(c[0], c[1]);
                    *(float2*)&Ds[(r + 8) * 50 + cc] = make_float2(c[2], c[3]);
                }
            }
            // wait for 3 peer partials
            if (tid == 0) {
                volatile unsigned* vf = &g_pflag[t][hs];
                while (*vf < 3u) __nanosleep(32);
            }
            __syncthreads();

            if (tid < 128) {
                const int row = tid;
                float df[48];
#pragma unroll
                for (int q = 0; q < 24; ++q) {
                    float2 v = *(const float2*)&Ds[row * 50 + q * 2];
                    df[q * 2] = v.x; df[q * 2 + 1] = v.y;
                }
                const float* pb = g_partial + (((size_t)hs * 2 + (t & 1)) * 3 * 128) * 48;
#pragma unroll
                for (int pi = 0; pi < 3; ++pi) {
                    const float* pp = pb + ((size_t)pi * 128 + row) * 48;
#pragma unroll
                    for (int q = 0; q < 12; ++q) {
                        float4 v = __ldcg((const float4*)pp + q);
                        df[q*4+0] += v.x; df[q*4+1] += v.y;
                        df[q*4+2] += v.z; df[q*4+3] += v.w;
                    }
                }
                // masked hprev
                const bool rst = resets[t * B_BATCH + row] != 0;
                float hp[16];
#pragma unroll
                for (int q = 0; q < 4; ++q) {
                    float4 v = *(const float4*)&g_hfp[(size_t)row * H_DIM + j0 + q * 4];
                    if (rst) { v.x = v.y = v.z = v.w = 0.f; }
                    hp[q*4+0]=v.x; hp[q*4+1]=v.y; hp[q*4+2]=v.z; hp[q*4+3]=v.w;
                }
                float hnew[16];
#pragma unroll
                for (int c = 0; c < 16; ++c) {
                    float r = 1.f / (1.f + __expf(-(xrv[c] + df[c])));
                    float z = 1.f / (1.f + __expf(-(xzv[c] + df[16 + c])));
                    float n = tanhf(xnv[c] + r * (df[32 + c] + bn_s[c]));
                    hnew[c] = (1.f - z) * n + z * hp[c];
                }
                // publish
                float* yrow = ys + ((size_t)t * B_BATCH + row) * H_DIM + j0;
                float* frow = g_hfp + (size_t)row * H_DIM + j0;
#pragma unroll
                for (int q = 0; q < 4; ++q) {
                    float4 v = make_float4(hnew[q*4+0], hnew[q*4+1], hnew[q*4+2], hnew[q*4+3]);
                    *((float4*)yrow + q) = v;
                    *((float4*)frow + q) = v;
                    if (t == T_STEPS - 1)
                        *((float4*)(hT + (size_t)row * H_DIM + j0) + q) = v;
                }
                uint32_t hw[8], lw[8];
#pragma unroll
                for (int c2 = 0; c2 < 8; ++c2) {
                    float v0 = hnew[c2 * 2], v1 = hnew[c2 * 2 + 1];
                    __nv_bfloat16 h0b = __float2bfloat16_rn(v0);
                    __nv_bfloat16 h1b = __float2bfloat16_rn(v1);
                    hw[c2] = (uint32_t)__bfloat16_as_ushort(h0b) |
                             ((uint32_t)__bfloat16_as_ushort(h1b) << 16);
                    lw[c2] = (uint32_t)__bfloat16_as_ushort(
                                 __float2bfloat16_rn(v0 - __bfloat162float(h0b))) |
                             ((uint32_t)__bfloat16_as_ushort(
                                 __float2bfloat16_rn(v1 - __bfloat162float(h1b))) << 16);
                }
                const int ob = t & 1;
                uint4* dh = (uint4*)(g_hhi[ob] + (size_t)row * H_DIM + j0);
                uint4* dl = (uint4*)(g_hlo[ob] + (size_t)row * H_DIM + j0);
                dh[0] = make_uint4(hw[0], hw[1], hw[2], hw[3]);
                dh[1] = make_uint4(hw[4], hw[5], hw[6], hw[7]);
                dl[0] = make_uint4(lw[0], lw[1], lw[2], lw[3]);
                dl[1] = make_uint4(lw[4], lw[5], lw[6], lw[7]);
            }
            __threadfence();
            __syncthreads();
            if (tid == 0) atomicAdd(&g_bar[t], 1u);
        }
    }
}

extern "C" void kernel_launch(void* const* d_in, const int* in_sizes, int n_in,
                              void* d_out, int out_size) {
    const float* ins    = (const float*)d_in[0];   // [T,B,D]
    const int*   resets = (const int*)  d_in[1];   // [T,B]
    const float* h0     = (const float*)d_in[2];   // [B,H]
    const float* Wi     = (const float*)d_in[3];   // [D,3H]
    const float* bi     = (const float*)d_in[4];   // [3H]
    const float* Whrz   = (const float*)d_in[5];   // [H,2H]
    const float* Whn    = (const float*)d_in[6];   // [H,H]
    const float* bhn    = (const float*)d_in[7];   // [H]
    float* out = (float*)d_out;

    (void)in_sizes; (void)n_in; (void)out_size;

    cudaFuncSetAttribute(xproj_kernel,
                         cudaFuncAttributeMaxDynamicSharedMemorySize, XP_SMEM_BYTES);
    cudaFuncSetAttribute(gru_kernel,
                         cudaFuncAttributeMaxDynamicSharedMemorySize, SC_SMEM);

    scan_prep_kernel<<<257, 256>>>(h0);
    {
        dim3 grid(1536 / 128, (T_STEPS * B_BATCH) / 128);
        xproj_kernel<<<grid, 256, XP_SMEM_BYTES>>>(ins, Wi, bi);
    }
    gru_kernel<<<128, 256, SC_SMEM>>>(resets, Whrz, Whn, bhn, out);
}

// round 8
// speedup vs baseline: 1.7547x; 1.7547x over previous
#include <cuda_runtime.h>
#include <cuda_bf16.h>
#include <cstdint>
#include <cstddef>

#define T_STEPS 512
#define B_BATCH 128
#define D_IN    512
#define H_DIM   512

// ---------------- device scratch (no-alloc rule) ----------------
__device__ float          g_xproj[(size_t)T_STEPS * B_BATCH * 3 * H_DIM]; // [T,B,3H]
__device__ __nv_bfloat16  g_hhi[2][(size_t)B_BATCH * H_DIM];  // [buf][row][k]
__device__ __nv_bfloat16  g_hlo[2][(size_t)B_BATCH * H_DIM];
__device__ float          g_hfp[(size_t)B_BATCH * H_DIM];     // fp32 h, row-major
__device__ unsigned       g_bar[T_STEPS][4];                  // [t][mi], 32 producers

// ---------- helpers ----------
static __device__ __forceinline__ uint32_t smem_u32(const void* p) {
    uint32_t a;
    asm("{ .reg .u64 t; cvta.to.shared.u64 t, %1; cvt.u32.u64 %0, t; }"
        : "=r"(a) : "l"(p));
    return a;
}
static __device__ __forceinline__ void ldsm_x4(uint32_t& r0, uint32_t& r1,
                                               uint32_t& r2, uint32_t& r3,
                                               uint32_t addr) {
    asm volatile("ldmatrix.sync.aligned.m8n8.x4.shared.b16 {%0,%1,%2,%3}, [%4];"
                 : "=r"(r0), "=r"(r1), "=r"(r2), "=r"(r3) : "r"(addr));
}
static __device__ __forceinline__ void mma_bf16(float& c0, float& c1, float& c2, float& c3,
                                                uint32_t a0, uint32_t a1, uint32_t a2, uint32_t a3,
                                                uint32_t b0, uint32_t b1) {
    asm volatile("mma.sync.aligned.m16n8k16.row.col.f32.bf16.bf16.f32 "
                 "{%0,%1,%2,%3}, {%4,%5,%6,%7}, {%8,%9}, {%0,%1,%2,%3};"
                 : "+f"(c0), "+f"(c1), "+f"(c2), "+f"(c3)
                 : "r"(a0), "r"(a1), "r"(a2), "r"(a3), "r"(b0), "r"(b1));
}
static __device__ __forceinline__ uint32_t bf16x2_of(float lo, float hi) {
    __nv_bfloat16 a = __float2bfloat16_rn(lo);
    __nv_bfloat16 b = __float2bfloat16_rn(hi);
    return (uint32_t)__bfloat16_as_ushort(a) | ((uint32_t)__bfloat16_as_ushort(b) << 16);
}

// ---------- prep: zero barriers; planes/hfp from h0 ----------
__global__ void scan_prep_kernel(const float* __restrict__ h0) {
    if (blockIdx.x == 0) {
        for (int i = threadIdx.x; i < T_STEPS * 4; i += 256)
            ((unsigned*)g_bar)[i] = 0u;
    } else {
        int idx = (blockIdx.x - 1) * 256 + threadIdx.x;   // row-major [row][k]
        float v = h0[idx];
        __nv_bfloat16 hi = __float2bfloat16_rn(v);
        g_hfp[idx] = v;
        g_hhi[1][idx] = hi;
        g_hlo[1][idx] = __float2bfloat16_rn(v - __bfloat162float(hi));
    }
}

// ---------------- x_proj GEMM via mma.sync split-bf16 (round-6, passing) ----------------
#define XP_ROWSTR 40
#define XP_PLANE  (128 * XP_ROWSTR)
#define XP_BUF    (4 * XP_PLANE)
#define XP_SMEM_BYTES (2 * XP_BUF * 2)

__global__ __launch_bounds__(256, 1) void xproj_kernel(const float* __restrict__ A,
                                                       const float* __restrict__ W,
                                                       const float* __restrict__ bi) {
    extern __shared__ __align__(16) __nv_bfloat16 sm[];
    const int tid = threadIdx.x;
    const int lane = tid & 31;
    const int wid = tid >> 5;
    const int warp_m = wid & 1;
    const int warp_n = wid >> 1;
    const int m0 = blockIdx.y * 128;
    const int n0 = blockIdx.x * 128;

    float acc[4][4][4];
#pragma unroll
    for (int i = 0; i < 4; ++i)
#pragma unroll
        for (int jn = 0; jn < 4; ++jn)
#pragma unroll
            for (int q = 0; q < 4; ++q) acc[i][jn][q] = 0.f;

    float2 ra[8];
    float  rw0[8], rw1[8];

    const uint32_t a_lane_off = (uint32_t)((lane & 15) * (XP_ROWSTR * 2) + (lane >> 4) * 16);
    const uint32_t b_lane_off = (uint32_t)(((lane & 7) + ((lane >> 4) << 3)) * (XP_ROWSTR * 2)
                                           + ((lane >> 3) & 1) * 16);
    const uint32_t sm_base = smem_u32(sm);

    {
        const int k0 = 0;
#pragma unroll
        for (int i = 0; i < 8; ++i) {
            int p = i * 256 + tid;
            int r = p >> 4, cp = p & 15;
            ra[i] = *(const float2*)&A[(size_t)(m0 + r) * D_IN + k0 + cp * 2];
            int n = p & 127, kp = p >> 7;
            rw0[i] = W[(size_t)(k0 + 2 * kp) * 1536 + n0 + n];
            rw1[i] = W[(size_t)(k0 + 2 * kp + 1) * 1536 + n0 + n];
        }
        uint32_t* AH = (uint32_t*)(sm);
        uint32_t* AL = (uint32_t*)(sm + XP_PLANE);
        uint32_t* WH = (uint32_t*)(sm + 2 * XP_PLANE);
        uint32_t* WL = (uint32_t*)(sm + 3 * XP_PLANE);
#pragma unroll
        for (int i = 0; i < 8; ++i) {
            int p = i * 256 + tid;
            int r = p >> 4, cp = p & 15;
            float h0v = __bfloat162float(__float2bfloat16_rn(ra[i].x));
            float h1v = __bfloat162float(__float2bfloat16_rn(ra[i].y));
            AH[r * (XP_ROWSTR / 2) + cp] = bf16x2_of(ra[i].x, ra[i].y);
            AL[r * (XP_ROWSTR / 2) + cp] = bf16x2_of(ra[i].x - h0v, ra[i].y - h1v);
            int n = p & 127, kp = p >> 7;
            float w0h = __bfloat162float(__float2bfloat16_rn(rw0[i]));
            float w1h = __bfloat162float(__float2bfloat16_rn(rw1[i]));
            WH[n * (XP_ROWSTR / 2) + kp] = bf16x2_of(rw0[i], rw1[i]);
            WL[n * (XP_ROWSTR / 2) + kp] = bf16x2_of(rw0[i] - w0h, rw1[i] - w1h);
        }
    }
    __syncthreads();

    int buf = 0;
    for (int kt = 0; kt < 16; ++kt) {
        if (kt < 15) {
            const int k0 = (kt + 1) * 32;
#pragma unroll
            for (int i = 0; i < 8; ++i) {
                int p = i * 256 + tid;
                int r = p >> 4, cp = p & 15;
                ra[i] = *(const float2*)&A[(size_t)(m0 + r) * D_IN + k0 + cp * 2];
                int n = p & 127, kp = p >> 7;
                rw0[i] = W[(size_t)(k0 + 2 * kp) * 1536 + n0 + n];
                rw1[i] = W[(size_t)(k0 + 2 * kp + 1) * 1536 + n0 + n];
            }
        }
        const uint32_t bb = sm_base + (uint32_t)(buf * XP_BUF * 2);
        const uint32_t baseAH = bb;
        const uint32_t baseAL = bb + XP_PLANE * 2;
        const uint32_t baseWH = bb + 2 * XP_PLANE * 2;
        const uint32_t baseWL = bb + 3 * XP_PLANE * 2;
#pragma unroll
        for (int k16 = 0; k16 < 2; ++k16) {
            const uint32_t kadd = (uint32_t)(k16 * 32);
            uint32_t ah[4][4], al[4][4], bh[4][2], bl[4][2];
#pragma unroll
            for (int mt = 0; mt < 4; ++mt) {
                uint32_t ro = (uint32_t)((warp_m * 64 + mt * 16) * (XP_ROWSTR * 2));
                ldsm_x4(ah[mt][0], ah[mt][1], ah[mt][2], ah[mt][3],
                        baseAH + ro + a_lane_off + kadd);
                ldsm_x4(al[mt][0], al[mt][1], al[mt][2], al[mt][3],
                        baseAL + ro + a_lane_off + kadd);
            }
#pragma unroll
            for (int nt2 = 0; nt2 < 2; ++nt2) {
                uint32_t no = (uint32_t)((warp_n * 32 + nt2 * 16) * (XP_ROWSTR * 2));
                ldsm_x4(bh[nt2 * 2][0], bh[nt2 * 2][1], bh[nt2 * 2 + 1][0], bh[nt2 * 2 + 1][1],
                        baseWH + no + b_lane_off + kadd);
                ldsm_x4(bl[nt2 * 2][0], bl[nt2 * 2][1], bl[nt2 * 2 + 1][0], bl[nt2 * 2 + 1][1],
                        baseWL + no + b_lane_off + kadd);
            }
#pragma unroll
            for (int mt = 0; mt < 4; ++mt)
#pragma unroll
                for (int nt = 0; nt < 4; ++nt) {
                    float* c = acc[mt][nt];
                    mma_bf16(c[0], c[1], c[2], c[3],
                             ah[mt][0], ah[mt][1], ah[mt][2], ah[mt][3],
                             bh[nt][0], bh[nt][1]);
                    mma_bf16(c[0], c[1], c[2], c[3],
                             al[mt][0], al[mt][1], al[mt][2], al[mt][3],
                             bh[nt][0], bh[nt][1]);
                    mma_bf16(c[0], c[1], c[2], c[3],
                             ah[mt][0], ah[mt][1], ah[mt][2], ah[mt][3],
                             bl[nt][0], bl[nt][1]);
                }
        }
        if (kt < 15) {
            __syncthreads();
            int nb = buf ^ 1;
            __nv_bfloat16* sb = sm + nb * XP_BUF;
            uint32_t* AH = (uint32_t*)(sb);
            uint32_t* AL = (uint32_t*)(sb + XP_PLANE);
            uint32_t* WH = (uint32_t*)(sb + 2 * XP_PLANE);
            uint32_t* WL = (uint32_t*)(sb + 3 * XP_PLANE);
#pragma unroll
            for (int i = 0; i < 8; ++i) {
                int p = i * 256 + tid;
                int r = p >> 4, cp = p & 15;
                float h0v = __bfloat162float(__float2bfloat16_rn(ra[i].x));
                float h1v = __bfloat162float(__float2bfloat16_rn(ra[i].y));
                AH[r * (XP_ROWSTR / 2) + cp] = bf16x2_of(ra[i].x, ra[i].y);
                AL[r * (XP_ROWSTR / 2) + cp] = bf16x2_of(ra[i].x - h0v, ra[i].y - h1v);
                int n = p & 127, kp = p >> 7;
                float w0h = __bfloat162float(__float2bfloat16_rn(rw0[i]));
                float w1h = __bfloat162float(__float2bfloat16_rn(rw1[i]));
                WH[n * (XP_ROWSTR / 2) + kp] = bf16x2_of(rw0[i], rw1[i]);
                WL[n * (XP_ROWSTR / 2) + kp] = bf16x2_of(rw0[i] - w0h, rw1[i] - w1h);
            }
            __syncthreads();
            buf = nb;
        }
    }

#pragma unroll
    for (int nt = 0; nt < 4; ++nt) {
        int ncol = warp_n * 32 + nt * 8 + (lane & 3) * 2;
        float2 bv = *(const float2*)&bi[n0 + ncol];
#pragma unroll
        for (int mt = 0; mt < 4; ++mt) {
            int r = m0 + warp_m * 64 + mt * 16 + (lane >> 2);
            float* c = acc[mt][nt];
            float2 o0; o0.x = c[0] + bv.x; o0.y = c[1] + bv.y;
            float2 o1; o1.x = c[2] + bv.x; o1.y = c[3] + bv.y;
            *(float2*)&g_xproj[(size_t)r * 1536 + n0 + ncol] = o0;
            *(float2*)&g_xproj[(size_t)(r + 8) * 1536 + n0 + ncol] = o1;
        }
    }
}

// ---------------- persistent mma.sync GRU scan (intra-CTA, round-4 topology) ----
// 128 CTAs: mi = bid>>5 (32 batch rows), hs = bid&31 (16 hid cols -> N=48).
// Per CTA: D[32,48] = A[32,512] @ W[512,48], warps split K (8 x 64).
// Split-bf16: Ah@Wh + Al@Wh + Ah@Wl. Warp partials reduced in smem.
#define SC_STR  1040                       // smem row stride bytes (512 bf16 + 16B pad)
#define SM_AH   0
#define SM_AL   (32 * SC_STR)              // 33280
#define SM_WH   (2 * 32 * SC_STR)          // 66560
#define SM_WL   (SM_WH + 48 * SC_STR)      // 116480
#define SC_SMEM (SM_WL + 48 * SC_STR)      // 166400
// partials P[8][32][50] fp32 overlay on A region (51200 <= 66560)

__global__ __launch_bounds__(256, 1) void gru_kernel(const int* __restrict__ resets,
                                                     const float* __restrict__ Whrz,
                                                     const float* __restrict__ Whn,
                                                     const float* __restrict__ bhn,
                                                     float* out) {
    extern __shared__ __align__(16) char smc[];
    const uint32_t sb = smem_u32(smc);
    float* P = (float*)(smc + SM_AH);      // overlay after MMA
    __shared__ float bn_s[16];

    const int tid = threadIdx.x;
    const int lane = tid & 31;
    const int wid = tid >> 5;              // K-chunk (0..7), 64 k each
    const int mi = blockIdx.x >> 5;
    const int hs = blockIdx.x & 31;
    const int j0 = hs * 16;

    float* hT = out;
    float* ys = out + (size_t)B_BATCH * H_DIM;

    if (tid < 16) bn_s[tid] = bhn[j0 + tid];

    // one-time: W slice (48 n x 512 k) hi/lo bf16, [n][k] stride 1040B
    for (int idx = tid; idx < 48 * 512; idx += 256) {
        int n = idx >> 9;
        int k = idx & 511;
        int gate = n >> 4;
        int col = j0 + (n & 15);
        float w;
        if (gate == 0)      w = Whrz[(size_t)k * 1024 + col];
        else if (gate == 1) w = Whrz[(size_t)k * 1024 + 512 + col];
        else                w = Whn[(size_t)k * 512 + col];
        __nv_bfloat16 whi = __float2bfloat16_rn(w);
        *(__nv_bfloat16*)(smc + SM_WH + n * SC_STR + k * 2) = whi;
        *(__nv_bfloat16*)(smc + SM_WL + n * SC_STR + k * 2) =
            __float2bfloat16_rn(w - __bfloat162float(whi));
    }
    __syncthreads();

    // ldmatrix lane offsets (validated mapping)
    const uint32_t a_off = (uint32_t)((lane & 15) * SC_STR + (lane >> 4) * 16);
    const uint32_t b4_off = (uint32_t)(((lane & 7) + ((lane >> 4) << 3)) * SC_STR
                                       + ((lane >> 3) & 1) * 16);

    // staging role: srow 0..31, kch 0..7 (64-k chunk = 128B per plane)
    const int srow = tid >> 3;
    const int kch = tid & 7;

    // gate role: 2 cols per thread
    const int gr = tid >> 3;               // 0..31
    const int gm = tid & 7;                // col pair
    const int grow = mi * 32 + gr;
    const int j0c = j0 + 2 * gm;

    for (int t = 0; t < T_STEPS; ++t) {
        // prefetch x-projection (independent of barrier)
        const float* xb = g_xproj + ((size_t)t * B_BATCH + grow) * 1536 + j0c;
        float2 xr2 = __ldcs((const float2*)(xb));
        float2 xz2 = __ldcs((const float2*)(xb + 512));
        float2 xn2 = __ldcs((const float2*)(xb + 1024));
        const bool grst = resets[t * B_BATCH + grow] != 0;

        // wait: all 32 producers of group mi at step t-1
        if (t > 0 && tid == 0) {
            volatile unsigned* vb = &g_bar[t - 1][mi];
            while (*vb < 32u) __nanosleep(32);
        }
        __syncthreads();

        // stage masked A [32 x 512] hi/lo; k-chunk-rotated 16B stores (conflict-free)
        {
            const int pb = (t + 1) & 1;
            const bool rst = resets[t * B_BATCH + mi * 32 + srow] != 0;
            const size_t go = (size_t)(mi * 32 + srow) * H_DIM + kch * 64;
            const uint4* ph = (const uint4*)(g_hhi[pb] + go);
            const uint4* pl = (const uint4*)(g_hlo[pb] + go);
            char* dh = smc + SM_AH + srow * SC_STR + kch * 128;
            char* dl = smc + SM_AL + srow * SC_STR + kch * 128;
#pragma unroll
            for (int ii = 0; ii < 8; ++ii) {
                const int i = (ii + kch) & 7;
                uint4 vh = __ldcg(ph + i);
                uint4 vl = __ldcg(pl + i);
                if (rst) { vh.x = vh.y = vh.z = vh.w = 0u; vl = vh; }
                *(uint4*)(dh + i * 16) = vh;
                *(uint4*)(dl + i * 16) = vl;
            }
        }
        __syncthreads();

        // MMA over this warp's K-chunk: M=32 (2 tiles) x N=48 (6 n8) x K=64
        float acc[2][6][4];
#pragma unroll
        for (int mt = 0; mt < 2; ++mt)
#pragma unroll
            for (int nt = 0; nt < 6; ++nt)
#pragma unroll
                for (int q = 0; q < 4; ++q) acc[mt][nt][q] = 0.f;

        const uint32_t kbase = (uint32_t)(wid * 128);
#pragma unroll
        for (int k16 = 0; k16 < 4; ++k16) {
            const uint32_t kadd = kbase + (uint32_t)(k16 * 32);
            uint32_t ah[2][4], al[2][4], bh[3][4], bl[3][4];
#pragma unroll
            for (int mt = 0; mt < 2; ++mt) {
                uint32_t ro = (uint32_t)(mt * 16 * SC_STR) + a_off + kadd;
                ldsm_x4(ah[mt][0], ah[mt][1], ah[mt][2], ah[mt][3], sb + SM_AH + ro);
                ldsm_x4(al[mt][0], al[mt][1], al[mt][2], al[mt][3], sb + SM_AL + ro);
            }
#pragma unroll
            for (int ng = 0; ng < 3; ++ng) {
                uint32_t no = (uint32_t)(ng * 16 * SC_STR) + b4_off + kadd;
                ldsm_x4(bh[ng][0], bh[ng][1], bh[ng][2], bh[ng][3], sb + SM_WH + no);
                ldsm_x4(bl[ng][0], bl[ng][1], bl[ng][2], bl[ng][3], sb + SM_WL + no);
            }
#pragma unroll
            for (int mt = 0; mt < 2; ++mt)
#pragma unroll
                for (int ng = 0; ng < 3; ++ng)
#pragma unroll
                    for (int half = 0; half < 2; ++half) {
                        float* c = acc[mt][ng * 2 + half];
                        mma_bf16(c[0], c[1], c[2], c[3],
                                 ah[mt][0], ah[mt][1], ah[mt][2], ah[mt][3],
                                 bh[ng][half * 2], bh[ng][half * 2 + 1]);
                        mma_bf16(c[0], c[1], c[2], c[3],
                                 al[mt][0], al[mt][1], al[mt][2], al[mt][3],
                                 bh[ng][half * 2], bh[ng][half * 2 + 1]);
                        mma_bf16(c[0], c[1], c[2], c[3],
                                 ah[mt][0], ah[mt][1], ah[mt][2], ah[mt][3],
                                 bl[ng][half * 2], bl[ng][half * 2 + 1]);
                    }
        }
        __syncthreads();   // A fully consumed -> safe to overlay partials

        // write warp partial P[wid][row][50]
#pragma unroll
        for (int mt = 0; mt < 2; ++mt) {
            int r = mt * 16 + (lane >> 2);
#pragma unroll
            for (int nt = 0; nt < 6; ++nt) {
                int cc = nt * 8 + (lane & 3) * 2;
                float* c = acc[mt][nt];
                *(float2*)&P[(wid * 32 + r) * 50 + cc] = make_float2(c[0], c[1]);
                *(float2*)&P[(wid * 32 + r + 8) * 50 + cc] = make_float2(c[2], c[3]);
            }
        }
        __syncthreads();

        // reduce 8 warp partials + gates for (grow, j0c, j0c+1)
        float dr0 = 0.f, dr1 = 0.f, dz0 = 0.f, dz1 = 0.f, dn0 = 0.f, dn1 = 0.f;
#pragma unroll
        for (int w = 0; w < 8; ++w) {
            const float* pr = P + (w * 32 + gr) * 50;
            float2 a = *(const float2*)&pr[2 * gm];
            float2 b = *(const float2*)&pr[16 + 2 * gm];
            float2 c = *(const float2*)&pr[32 + 2 * gm];
            dr0 += a.x; dr1 += a.y;
            dz0 += b.x; dz1 += b.y;
            dn0 += c.x; dn1 += c.y;
        }

        float2 hpv = *(const float2*)&g_hfp[(size_t)grow * H_DIM + j0c];
        if (grst) { hpv.x = 0.f; hpv.y = 0.f; }

        float rg0 = 1.f / (1.f + __expf(-(xr2.x + dr0)));
        float zg0 = 1.f / (1.f + __expf(-(xz2.x + dz0)));
        float ng0 = tanhf(xn2.x + rg0 * (dn0 + bn_s[2 * gm]));
        float h0n = (1.f - zg0) * ng0 + zg0 * hpv.x;

        float rg1 = 1.f / (1.f + __expf(-(xr2.y + dr1)));
        float zg1 = 1.f / (1.f + __expf(-(xz2.y + dz1)));
        float ng1 = tanhf(xn2.y + rg1 * (dn1 + bn_s[2 * gm + 1]));
        float h1n = (1.f - zg1) * ng1 + zg1 * hpv.y;

        // publish
        float2 o; o.x = h0n; o.y = h1n;
        *(float2*)&ys[((size_t)t * B_BATCH + grow) * H_DIM + j0c] = o;
        *(float2*)&g_hfp[(size_t)grow * H_DIM + j0c] = o;
        const int ob = t & 1;
        __nv_bfloat16 b0 = __float2bfloat16_rn(h0n);
        __nv_bfloat16 b1 = __float2bfloat16_rn(h1n);
        *(uint32_t*)&g_hhi[ob][(size_t)grow * H_DIM + j0c] =
            (uint32_t)__bfloat16_as_ushort(b0) | ((uint32_t)__bfloat16_as_ushort(b1) << 16);
        *(uint32_t*)&g_hlo[ob][(size_t)grow * H_DIM + j0c] =
            (uint32_t)__bfloat16_as_ushort(__float2bfloat16_rn(h0n - __bfloat162float(b0))) |
            ((uint32_t)__bfloat16_as_ushort(__float2bfloat16_rn(h1n - __bfloat162float(b1))) << 16);
        if (t == T_STEPS - 1)
            *(float2*)&hT[(size_t)grow * H_DIM + j0c] = o;

        __threadfence();
        __syncthreads();
        if (tid == 0) atomicAdd(&g_bar[t][mi], 1u);
    }
}

extern "C" void kernel_launch(void* const* d_in, const int* in_sizes, int n_in,
                              void* d_out, int out_size) {
    const float* ins    = (const float*)d_in[0];   // [T,B,D]
    const int*   resets = (const int*)  d_in[1];   // [T,B]
    const float* h0     = (const float*)d_in[2];   // [B,H]
    const float* Wi     = (const float*)d_in[3];   // [D,3H]
    const float* bi     = (const float*)d_in[4];   // [3H]
    const float* Whrz   = (const float*)d_in[5];   // [H,2H]
    const float* Whn    = (const float*)d_in[6];   // [H,H]
    const float* bhn    = (const float*)d_in[7];   // [H]
    float* out = (float*)d_out;

    (void)in_sizes; (void)n_in; (void)out_size;

    cudaFuncSetAttribute(xproj_kernel,
                         cudaFuncAttributeMaxDynamicSharedMemorySize, XP_SMEM_BYTES);
    cudaFuncSetAttribute(gru_kernel,
                         cudaFuncAttributeMaxDynamicSharedMemorySize, SC_SMEM);

    scan_prep_kernel<<<257, 256>>>(h0);
    {
        dim3 grid(1536 / 128, (T_STEPS * B_BATCH) / 128);
        xproj_kernel<<<grid, 256, XP_SMEM_BYTES>>>(ins, Wi, bi);
    }
    gru_kernel<<<128, 256, SC_SMEM>>>(resets, Whrz, Whn, bhn, out);
}

// round 9
// speedup vs baseline: 1.7590x; 1.0024x over previous
#include <cuda_runtime.h>
#include <cuda_bf16.h>
#include <cstdint>
#include <cstddef>

#define T_STEPS 512
#define B_BATCH 128
#define D_IN    512
#define H_DIM   512

// ---------------- device scratch (no-alloc rule) ----------------
__device__ float          g_xproj[(size_t)T_STEPS * B_BATCH * 3 * H_DIM]; // [T,B,3H]
__device__ __nv_bfloat16  g_hhi[2][(size_t)B_BATCH * H_DIM];  // [buf][row][k]
__device__ __nv_bfloat16  g_hlo[2][(size_t)B_BATCH * H_DIM];
__device__ unsigned       g_bar[T_STEPS][4];                  // [t][mi], 32 producers
// pre-converted bf16x2 planes for xproj
__device__ uint32_t       g_ahi[(size_t)T_STEPS * B_BATCH * 256];  // A hi [row][kpair]
__device__ uint32_t       g_alo[(size_t)T_STEPS * B_BATCH * 256];
__device__ uint32_t       g_whi[1536 * 256];                       // W hi, [n][kpair]
__device__ uint32_t       g_wlo[1536 * 256];

// ---------- helpers ----------
static __device__ __forceinline__ uint32_t smem_u32(const void* p) {
    uint32_t a;
    asm("{ .reg .u64 t; cvta.to.shared.u64 t, %1; cvt.u32.u64 %0, t; }"
        : "=r"(a) : "l"(p));
    return a;
}
static __device__ __forceinline__ void ldsm_x4(uint32_t& r0, uint32_t& r1,
                                               uint32_t& r2, uint32_t& r3,
                                               uint32_t addr) {
    asm volatile("ldmatrix.sync.aligned.m8n8.x4.shared.b16 {%0,%1,%2,%3}, [%4];"
                 : "=r"(r0), "=r"(r1), "=r"(r2), "=r"(r3) : "r"(addr));
}
static __device__ __forceinline__ void mma_bf16(float& c0, float& c1, float& c2, float& c3,
                                                uint32_t a0, uint32_t a1, uint32_t a2, uint32_t a3,
                                                uint32_t b0, uint32_t b1) {
    asm volatile("mma.sync.aligned.m16n8k16.row.col.f32.bf16.bf16.f32 "
                 "{%0,%1,%2,%3}, {%4,%5,%6,%7}, {%8,%9}, {%0,%1,%2,%3};"
                 : "+f"(c0), "+f"(c1), "+f"(c2), "+f"(c3)
                 : "r"(a0), "r"(a1), "r"(a2), "r"(a3), "r"(b0), "r"(b1));
}
static __device__ __forceinline__ uint32_t bf16x2_of(float lo, float hi) {
    __nv_bfloat16 a = __float2bfloat16_rn(lo);
    __nv_bfloat16 b = __float2bfloat16_rn(hi);
    return (uint32_t)__bfloat16_as_ushort(a) | ((uint32_t)__bfloat16_as_ushort(b) << 16);
}

// ---------- prep: zero barriers; h planes from h0 ----------
__global__ void scan_prep_kernel(const float* __restrict__ h0) {
    if (blockIdx.x == 0) {
        for (int i = threadIdx.x; i < T_STEPS * 4; i += 256)
            ((unsigned*)g_bar)[i] = 0u;
    } else {
        int idx = (blockIdx.x - 1) * 256 + threadIdx.x;   // row-major [row][k]
        float v = h0[idx];
        __nv_bfloat16 hi = __float2bfloat16_rn(v);
        g_hhi[1][idx] = hi;
        g_hlo[1][idx] = __float2bfloat16_rn(v - __bfloat162float(hi));
    }
}

// ---------- conv: A [65536][512] fp32 -> hi/lo bf16x2 planes [row][256] ----------
__global__ void conv_a_kernel(const float* __restrict__ A) {
    size_t idx = (size_t)blockIdx.x * 256 + threadIdx.x;   // row*256 + kpair
    float2 v = ((const float2*)A)[idx];
    __nv_bfloat16 h0b = __float2bfloat16_rn(v.x);
    __nv_bfloat16 h1b = __float2bfloat16_rn(v.y);
    g_ahi[idx] = (uint32_t)__bfloat16_as_ushort(h0b) |
                 ((uint32_t)__bfloat16_as_ushort(h1b) << 16);
    g_alo[idx] = bf16x2_of(v.x - __bfloat162float(h0b), v.y - __bfloat162float(h1b));
}

// ---------- conv: W [512][1536] fp32 -> transposed hi/lo planes [n][256 kpair] ----------
__global__ void conv_w_kernel(const float* __restrict__ W) {
    int n = blockIdx.x;          // 0..1535
    int kp = threadIdx.x;        // 0..255
    float w0 = W[(size_t)(2 * kp) * 1536 + n];
    float w1 = W[(size_t)(2 * kp + 1) * 1536 + n];
    __nv_bfloat16 h0b = __float2bfloat16_rn(w0);
    __nv_bfloat16 h1b = __float2bfloat16_rn(w1);
    g_whi[n * 256 + kp] = (uint32_t)__bfloat16_as_ushort(h0b) |
                          ((uint32_t)__bfloat16_as_ushort(h1b) << 16);
    g_wlo[n * 256 + kp] = bf16x2_of(w0 - __bfloat162float(h0b), w1 - __bfloat162float(h1b));
}

// ---------------- x_proj GEMM via mma.sync split-bf16 (plane-fed staging) -----
#define XP_ROWSTR 40
#define XP_PLANE  (128 * XP_ROWSTR)
#define XP_BUF    (4 * XP_PLANE)
#define XP_SMEM_BYTES (2 * XP_BUF * 2)

__global__ __launch_bounds__(256, 1) void xproj_kernel(const float* __restrict__ bi) {
    extern __shared__ __align__(16) __nv_bfloat16 sm[];
    const int tid = threadIdx.x;
    const int lane = tid & 31;
    const int wid = tid >> 5;
    const int warp_m = wid & 1;
    const int warp_n = wid >> 1;
    const int m0 = blockIdx.y * 128;
    const int n0 = blockIdx.x * 128;

    float acc[4][4][4];
#pragma unroll
    for (int i = 0; i < 4; ++i)
#pragma unroll
        for (int jn = 0; jn < 4; ++jn)
#pragma unroll
            for (int q = 0; q < 4; ++q) acc[i][jn][q] = 0.f;

    uint32_t rah[8], ral[8], rwh[8], rwl[8];

    // staging maps: A: r = p>>4, cp = p&15 ; W: kp = p&15, n = p>>4
    const int a_r = tid >> 4, a_cp = tid & 15;
    const int w_kp = tid & 15, w_n = tid >> 4;

    const uint32_t a_lane_off = (uint32_t)((lane & 15) * (XP_ROWSTR * 2) + (lane >> 4) * 16);
    const uint32_t b_lane_off = (uint32_t)(((lane & 7) + ((lane >> 4) << 3)) * (XP_ROWSTR * 2)
                                           + ((lane >> 3) & 1) * 16);
    const uint32_t sm_base = smem_u32(sm);

    // stage chunk 0 into buffer 0
    {
        const int kw = 0;  // kpair base = kt*16
        uint32_t* AH = (uint32_t*)(sm);
        uint32_t* AL = (uint32_t*)(sm + XP_PLANE);
        uint32_t* WH = (uint32_t*)(sm + 2 * XP_PLANE);
        uint32_t* WL = (uint32_t*)(sm + 3 * XP_PLANE);
#pragma unroll
        for (int i = 0; i < 8; ++i) {
            int r = i * 16 + a_r;         // a_r strides 0..15 within each i? no:
            (void)r;
        }
        // A: 8 iters cover 128 rows x 16 kpairs
#pragma unroll
        for (int i = 0; i < 8; ++i) {
            int rr = a_r + i * 16;
            size_t gi = (size_t)(m0 + rr) * 256 + kw + a_cp;
            AH[rr * 20 + a_cp] = g_ahi[gi];
            AL[rr * 20 + a_cp] = g_alo[gi];
        }
        // W: 8 iters cover 128 n x 16 kpairs
#pragma unroll
        for (int i = 0; i < 8; ++i) {
            int nn = w_n + i * 16;
            size_t gi = (size_t)(n0 + nn) * 256 + kw + w_kp;
            WH[nn * 20 + w_kp] = g_whi[gi];
            WL[nn * 20 + w_kp] = g_wlo[gi];
        }
    }
    __syncthreads();

    int buf = 0;
    for (int kt = 0; kt < 16; ++kt) {
        if (kt < 15) {
            const int kw = (kt + 1) * 16;
#pragma unroll
            for (int i = 0; i < 8; ++i) {
                int rr = a_r + i * 16;
                size_t gi = (size_t)(m0 + rr) * 256 + kw + a_cp;
                rah[i] = g_ahi[gi];
                ral[i] = g_alo[gi];
                int nn = w_n + i * 16;
                size_t gw = (size_t)(n0 + nn) * 256 + kw + w_kp;
                rwh[i] = g_whi[gw];
                rwl[i] = g_wlo[gw];
            }
        }
        const uint32_t bb = sm_base + (uint32_t)(buf * XP_BUF * 2);
        const uint32_t baseAH = bb;
        const uint32_t baseAL = bb + XP_PLANE * 2;
        const uint32_t baseWH = bb + 2 * XP_PLANE * 2;
        const uint32_t baseWL = bb + 3 * XP_PLANE * 2;
#pragma unroll
        for (int k16 = 0; k16 < 2; ++k16) {
            const uint32_t kadd = (uint32_t)(k16 * 32);
            uint32_t ah[4][4], al[4][4], bh[4][2], bl[4][2];
#pragma unroll
            for (int mt = 0; mt < 4; ++mt) {
                uint32_t ro = (uint32_t)((warp_m * 64 + mt * 16) * (XP_ROWSTR * 2));
                ldsm_x4(ah[mt][0], ah[mt][1], ah[mt][2], ah[mt][3],
                        baseAH + ro + a_lane_off + kadd);
                ldsm_x4(al[mt][0], al[mt][1], al[mt][2], al[mt][3],
                        baseAL + ro + a_lane_off + kadd);
            }
#pragma unroll
            for (int nt2 = 0; nt2 < 2; ++nt2) {
                uint32_t no = (uint32_t)((warp_n * 32 + nt2 * 16) * (XP_ROWSTR * 2));
                ldsm_x4(bh[nt2 * 2][0], bh[nt2 * 2][1], bh[nt2 * 2 + 1][0], bh[nt2 * 2 + 1][1],
                        baseWH + no + b_lane_off + kadd);
                ldsm_x4(bl[nt2 * 2][0], bl[nt2 * 2][1], bl[nt2 * 2 + 1][0], bl[nt2 * 2 + 1][1],
                        baseWL + no + b_lane_off + kadd);
            }
#pragma unroll
            for (int mt = 0; mt < 4; ++mt)
#pragma unroll
                for (int nt = 0; nt < 4; ++nt) {
                    float* c = acc[mt][nt];
                    mma_bf16(c[0], c[1], c[2], c[3],
                             ah[mt][0], ah[mt][1], ah[mt][2], ah[mt][3],
                             bh[nt][0], bh[nt][1]);
                    mma_bf16(c[0], c[1], c[2], c[3],
                             al[mt][0], al[mt][1], al[mt][2], al[mt][3],
                             bh[nt][0], bh[nt][1]);
                    mma_bf16(c[0], c[1], c[2], c[3],
                             ah[mt][0], ah[mt][1], ah[mt][2], ah[mt][3],
                             bl[nt][0], bl[nt][1]);
                }
        }
        if (kt < 15) {
            __syncthreads();
            int nb = buf ^ 1;
            __nv_bfloat16* sb = sm + nb * XP_BUF;
            uint32_t* AH = (uint32_t*)(sb);
            uint32_t* AL = (uint32_t*)(sb + XP_PLANE);
            uint32_t* WH = (uint32_t*)(sb + 2 * XP_PLANE);
            uint32_t* WL = (uint32_t*)(sb + 3 * XP_PLANE);
#pragma unroll
            for (int i = 0; i < 8; ++i) {
                int rr = a_r + i * 16;
                AH[rr * 20 + a_cp] = rah[i];
                AL[rr * 20 + a_cp] = ral[i];
                int nn = w_n + i * 16;
                WH[nn * 20 + w_kp] = rwh[i];
                WL[nn * 20 + w_kp] = rwl[i];
            }
            __syncthreads();
            buf = nb;
        }
    }

#pragma unroll
    for (int nt = 0; nt < 4; ++nt) {
        int ncol = warp_n * 32 + nt * 8 + (lane & 3) * 2;
        float2 bv = *(const float2*)&bi[n0 + ncol];
#pragma unroll
        for (int mt = 0; mt < 4; ++mt) {
            int r = m0 + warp_m * 64 + mt * 16 + (lane >> 2);
            float* c = acc[mt][nt];
            float2 o0; o0.x = c[0] + bv.x; o0.y = c[1] + bv.y;
            float2 o1; o1.x = c[2] + bv.x; o1.y = c[3] + bv.y;
            *(float2*)&g_xproj[(size_t)r * 1536 + n0 + ncol] = o0;
            *(float2*)&g_xproj[(size_t)(r + 8) * 1536 + n0 + ncol] = o1;
        }
    }
}

// ---------------- persistent mma.sync GRU scan ----------------
// 128 CTAs: mi = bid>>5 (32 batch rows), hs = bid&31 (16 hid cols -> N=48).
// Per-warp independent staging of its own K-chunk; hprev in registers.
#define SC_STR  1040
#define SM_AH   0
#define SM_AL   (32 * SC_STR)
#define SM_WH   (2 * 32 * SC_STR)
#define SM_WL   (SM_WH + 48 * SC_STR)
#define SC_SMEM (SM_WL + 48 * SC_STR)      // 166400
// partials P[8][32][50] fp32 overlay on A region (51200 <= 66560)

__global__ __launch_bounds__(256, 1) void gru_kernel(const int* __restrict__ resets,
                                                     const float* __restrict__ h0g,
                                                     const float* __restrict__ Whrz,
                                                     const float* __restrict__ Whn,
                                                     const float* __restrict__ bhn,
                                                     float* out) {
    extern __shared__ __align__(16) char smc[];
    const uint32_t sb = smem_u32(smc);
    float* P = (float*)(smc + SM_AH);
    __shared__ float bn_s[16];

    const int tid = threadIdx.x;
    const int lane = tid & 31;
    const int wid = tid >> 5;
    const int mi = blockIdx.x >> 5;
    const int hs = blockIdx.x & 31;
    const int j0 = hs * 16;

    float* hT = out;
    float* ys = out + (size_t)B_BATCH * H_DIM;

    if (tid < 16) bn_s[tid] = bhn[j0 + tid];

    // one-time: W slice (48 n x 512 k) hi/lo bf16
    for (int idx = tid; idx < 48 * 512; idx += 256) {
        int n = idx >> 9;
        int k = idx & 511;
        int gate = n >> 4;
        int col = j0 + (n & 15);
        float w;
        if (gate == 0)      w = Whrz[(size_t)k * 1024 + col];
        else if (gate == 1) w = Whrz[(size_t)k * 1024 + 512 + col];
        else                w = Whn[(size_t)k * 512 + col];
        __nv_bfloat16 whi = __float2bfloat16_rn(w);
        *(__nv_bfloat16*)(smc + SM_WH + n * SC_STR + k * 2) = whi;
        *(__nv_bfloat16*)(smc + SM_WL + n * SC_STR + k * 2) =
            __float2bfloat16_rn(w - __bfloat162float(whi));
    }
    __syncthreads();

    const uint32_t a_off = (uint32_t)((lane & 15) * SC_STR + (lane >> 4) * 16);
    const uint32_t b4_off = (uint32_t)(((lane & 7) + ((lane >> 4) << 3)) * SC_STR
                                       + ((lane >> 3) & 1) * 16);

    // gate role
    const int gr = tid >> 3;
    const int gm = tid & 7;
    const int grow = mi * 32 + gr;
    const int j0c = j0 + 2 * gm;

    float hp0r = 0.f, hp1r = 0.f;    // register hprev (set at t=0 from h0)

    for (int t = 0; t < T_STEPS; ++t) {
        // prefetch (barrier-independent): x-projection, reset flags
        const float* xb = g_xproj + ((size_t)t * B_BATCH + grow) * 1536 + j0c;
        float2 xr2 = __ldcs((const float2*)(xb));
        float2 xz2 = __ldcs((const float2*)(xb + 512));
        float2 xn2 = __ldcs((const float2*)(xb + 1024));
        const bool grst = resets[t * B_BATCH + grow] != 0;
        const bool srst = resets[t * B_BATCH + mi * 32 + lane] != 0;
        if (t == 0) {
            float2 hv = *(const float2*)&h0g[(size_t)grow * H_DIM + j0c];
            hp0r = hv.x; hp1r = hv.y;
        }

        // wait: 32 producers of group mi at step t-1
        if (t > 0 && tid == 0) {
            volatile unsigned* vb = &g_bar[t - 1][mi];
            while (*vb < 32u) __nanosleep(32);
        }
        __syncthreads();

        // per-warp staging: warp wid stages A[32 rows][wid*64 .. +64) hi/lo
        {
            const int pb = (t + 1) & 1;
            const size_t go = (size_t)(mi * 32 + lane) * H_DIM + wid * 64;
            const uint4* ph = (const uint4*)(g_hhi[pb] + go);
            const uint4* pl = (const uint4*)(g_hlo[pb] + go);
            char* dh = smc + SM_AH + lane * SC_STR + wid * 128;
            char* dl = smc + SM_AL + lane * SC_STR + wid * 128;
            uint4 vh[8], vl[8];
#pragma unroll
            for (int i = 0; i < 8; ++i) { vh[i] = __ldcg(ph + i); vl[i] = __ldcg(pl + i); }
            if (srst) {
#pragma unroll
                for (int i = 0; i < 8; ++i) {
                    vh[i].x = vh[i].y = vh[i].z = vh[i].w = 0u;
                    vl[i] = vh[i];
                }
            }
#pragma unroll
            for (int i = 0; i < 8; ++i) {
                *(uint4*)(dh + i * 16) = vh[i];
                *(uint4*)(dl + i * 16) = vl[i];
            }
            __syncwarp();
        }

        // MMA on own K-chunk: M=32 x N=48 x K=64, split-bf16
        float acc[2][6][4];
#pragma unroll
        for (int mt = 0; mt < 2; ++mt)
#pragma unroll
            for (int nt = 0; nt < 6; ++nt)
#pragma unroll
                for (int q = 0; q < 4; ++q) acc[mt][nt][q] = 0.f;

        const uint32_t kbase = (uint32_t)(wid * 128);
#pragma unroll
        for (int k16 = 0; k16 < 4; ++k16) {
            const uint32_t kadd = kbase + (uint32_t)(k16 * 32);
            uint32_t ah[2][4], al[2][4], bh[3][4], bl[3][4];
#pragma unroll
            for (int mt = 0; mt < 2; ++mt) {
                uint32_t ro = (uint32_t)(mt * 16 * SC_STR) + a_off + kadd;
                ldsm_x4(ah[mt][0], ah[mt][1], ah[mt][2], ah[mt][3], sb + SM_AH + ro);
                ldsm_x4(al[mt][0], al[mt][1], al[mt][2], al[mt][3], sb + SM_AL + ro);
            }
#pragma unroll
            for (int ng = 0; ng < 3; ++ng) {
                uint32_t no = (uint32_t)(ng * 16 * SC_STR) + b4_off + kadd;
                ldsm_x4(bh[ng][0], bh[ng][1], bh[ng][2], bh[ng][3], sb + SM_WH + no);
                ldsm_x4(bl[ng][0], bl[ng][1], bl[ng][2], bl[ng][3], sb + SM_WL + no);
            }
#pragma unroll
            for (int mt = 0; mt < 2; ++mt)
#pragma unroll
                for (int ng = 0; ng < 3; ++ng)
#pragma unroll
                    for (int half = 0; half < 2; ++half) {
                        float* c = acc[mt][ng * 2 + half];
                        mma_bf16(c[0], c[1], c[2], c[3],
                                 ah[mt][0], ah[mt][1], ah[mt][2], ah[mt][3],
                                 bh[ng][half * 2], bh[ng][half * 2 + 1]);
                        mma_bf16(c[0], c[1], c[2], c[3],
                                 al[mt][0], al[mt][1], al[mt][2], al[mt][3],
                                 bh[ng][half * 2], bh[ng][half * 2 + 1]);
                        mma_bf16(c[0], c[1], c[2], c[3],
                                 ah[mt][0], ah[mt][1], ah[mt][2], ah[mt][3],
                                 bl[ng][half * 2], bl[ng][half * 2 + 1]);
                    }
        }
        __syncthreads();   // all warps done with A -> overlay partials

        // warp partial P[wid][row][50]
#pragma unroll
        for (int mt = 0; mt < 2; ++mt) {
            int r = mt * 16 + (lane >> 2);
#pragma unroll
            for (int nt = 0; nt < 6; ++nt) {
                int cc = nt * 8 + (lane & 3) * 2;
                float* c = acc[mt][nt];
                *(float2*)&P[(wid * 32 + r) * 50 + cc] = make_float2(c[0], c[1]);
                *(float2*)&P[(wid * 32 + r + 8) * 50 + cc] = make_float2(c[2], c[3]);
            }
        }
        __syncthreads();

        // reduce 8 warp partials + gates
        float dr0 = 0.f, dr1 = 0.f, dz0 = 0.f, dz1 = 0.f, dn0 = 0.f, dn1 = 0.f;
#pragma unroll
        for (int w = 0; w < 8; ++w) {
            const float* pr = P + (w * 32 + gr) * 50;
            float2 a = *(const float2*)&pr[2 * gm];
            float2 b = *(const float2*)&pr[16 + 2 * gm];
            float2 c = *(const float2*)&pr[32 + 2 * gm];
            dr0 += a.x; dr1 += a.y;
            dz0 += b.x; dz1 += b.y;
            dn0 += c.x; dn1 += c.y;
        }

        float hpx = grst ? 0.f : hp0r;
        float hpy = grst ? 0.f : hp1r;

        float rg0 = 1.f / (1.f + __expf(-(xr2.x + dr0)));
        float zg0 = 1.f / (1.f + __expf(-(xz2.x + dz0)));
        float ng0 = tanhf(xn2.x + rg0 * (dn0 + bn_s[2 * gm]));
        float h0n = (1.f - zg0) * ng0 + zg0 * hpx;

        float rg1 = 1.f / (1.f + __expf(-(xr2.y + dr1)));
        float zg1 = 1.f / (1.f + __expf(-(xz2.y + dz1)));
        float ng1 = tanhf(xn2.y + rg1 * (dn1 + bn_s[2 * gm + 1]));
        float h1n = (1.f - zg1) * ng1 + zg1 * hpy;

        hp0r = h0n; hp1r = h1n;

        // publish: ys + bf16 planes (+hT at last step)
        float2 o; o.x = h0n; o.y = h1n;
        *(float2*)&ys[((size_t)t * B_BATCH + grow) * H_DIM + j0c] = o;
        const int ob = t & 1;
        __nv_bfloat16 b0 = __float2bfloat16_rn(h0n);
        __nv_bfloat16 b1 = __float2bfloat16_rn(h1n);
        *(uint32_t*)&g_hhi[ob][(size_t)grow * H_DIM + j0c] =
            (uint32_t)__bfloat16_as_ushort(b0) | ((uint32_t)__bfloat16_as_ushort(b1) << 16);
        *(uint32_t*)&g_hlo[ob][(size_t)grow * H_DIM + j0c] =
            (uint32_t)__bfloat16_as_ushort(__float2bfloat16_rn(h0n - __bfloat162float(b0))) |
            ((uint32_t)__bfloat16_as_ushort(__float2bfloat16_rn(h1n - __bfloat162float(b1))) << 16);
        if (t == T_STEPS - 1)
            *(float2*)&hT[(size_t)grow * H_DIM + j0c] = o;

        __threadfence();
        __syncthreads();
        if (tid == 0) atomicAdd(&g_bar[t][mi], 1u);
    }
}

extern "C" void kernel_launch(void* const* d_in, const int* in_sizes, int n_in,
                              void* d_out, int out_size) {
    const float* ins    = (const float*)d_in[0];   // [T,B,D]
    const int*   resets = (const int*)  d_in[1];   // [T,B]
    const float* h0     = (const float*)d_in[2];   // [B,H]
    const float* Wi     = (const float*)d_in[3];   // [D,3H]
    const float* bi     = (const float*)d_in[4];   // [3H]
    const float* Whrz   = (const float*)d_in[5];   // [H,2H]
    const float* Whn    = (const float*)d_in[6];   // [H,H]
    const float* bhn    = (const float*)d_in[7];   // [H]
    float* out = (float*)d_out;

    (void)in_sizes; (void)n_in; (void)out_size;

    cudaFuncSetAttribute(xproj_kernel,
                         cudaFuncAttributeMaxDynamicSharedMemorySize, XP_SMEM_BYTES);
    cudaFuncSetAttribute(gru_kernel,
                         cudaFuncAttributeMaxDynamicSharedMemorySize, SC_SMEM);

    scan_prep_kernel<<<257, 256>>>(h0);
    conv_a_kernel<<<65536, 256>>>(ins);
    conv_w_kernel<<<1536, 256>>>(Wi);
    {
        dim3 grid(1536 / 128, (T_STEPS * B_BATCH) / 128);
        xproj_kernel<<<grid, 256, XP_SMEM_BYTES>>>(bi);
    }
    gru_kernel<<<128, 256, SC_SMEM>>>(resets, h0, Whrz, Whn, bhn, out);
}